// round 6
// baseline (speedup 1.0000x reference)
#include <cuda_runtime.h>
#include <math.h>

#define BB 16      // batch
#define TT 1024    // sequence
#define JJ 128     // input dim
#define HH 64      // hidden (complex) dim

// Per-(b, segment) published inclusive state E (complex, 64 h) + ready flags.
__device__ __align__(16) float2 g_C[BB * 8 * HH];
__device__ unsigned g_flag[BB * 8];

// ---------------------------------------------------------------------------
// tf32 helpers
// ---------------------------------------------------------------------------
__device__ __forceinline__ unsigned tf32bits(float v) {
    unsigned r;
    asm("cvt.rna.tf32.f32 %0, %1;" : "=r"(r) : "f"(v));
    return r;
}
__device__ __forceinline__ void mma_tf32(float& d0, float& d1, float& d2, float& d3,
                                         unsigned a0, unsigned a1, unsigned a2, unsigned a3,
                                         unsigned b0, unsigned b1) {
    asm("mma.sync.aligned.m16n8k8.row.col.f32.tf32.tf32.f32 "
        "{%0,%1,%2,%3}, {%4,%5,%6,%7}, {%8,%9}, {%0,%1,%2,%3};"
        : "+f"(d0), "+f"(d1), "+f"(d2), "+f"(d3)
        : "r"(a0), "r"(a1), "r"(a2), "r"(a3), "r"(b0), "r"(b1));
}
__device__ __forceinline__ unsigned fbits(float v) { return __float_as_uint(v); }

// ---------------------------------------------------------------------------
// Prologue: reset lookback flags (graph-replay safe).
// ---------------------------------------------------------------------------
__global__ void reset_kernel() { g_flag[threadIdx.x] = 0u; }

// ---------------------------------------------------------------------------
// K1: fused GEMM (3xTF32) + segment scan with decoupled lookback.
// Grid 128 = 16 b x 8 t-segments (128 t each), 256 threads, ALL RESIDENT
// (single wave) -> cross-block forward chaining is deadlock-free.
// ---------------------------------------------------------------------------
#define KST 68
#define K1_SMEM_BYTES (384 * KST * 4)   // xhi(128)+xlo(128)+bhi(64)+blo(64) rows

__global__ __launch_bounds__(256) void fused_kernel(const float* __restrict__ x,
                                                    const float* __restrict__ Bm,
                                                    const float* __restrict__ nu,
                                                    const float* __restrict__ theta,
                                                    float* __restrict__ out) {
    extern __shared__ __align__(16) float sm[];
    float* xhi = sm;                    // [t 0..127][j 0..63] stride 68
    float* xlo = sm + 128 * KST;
    float* bhi = sm + 256 * KST;        // [h 0..63][j 0..63] stride 68
    float* blo = sm + 320 * KST;

    __shared__ float Vr_s[4 * 64], Vi_s[4 * 64];
    __shared__ float Wr_s[4 * 64], Wi_s[4 * 64];
    __shared__ float Ssr[64], Ssi[64];      // incoming segment state S

    const int tid  = threadIdx.x;
    const int lane = tid & 31;
    const int wid  = tid >> 5;
    const int wt   = wid >> 1;          // 0..3 -> 32 t
    const int wh   = wid & 1;           // 0..1 -> 32 h
    const int b    = blockIdx.x >> 3;
    const int ts   = blockIdx.x & 7;
    const int t0   = ts * 128;
    const int lr   = lane >> 2;         // 0..7
    const int lc   = lane & 3;          // 0..3

    float acc[2][4][4];
#pragma unroll
    for (int m = 0; m < 2; ++m)
#pragma unroll
        for (int n = 0; n < 4; ++n)
#pragma unroll
            for (int q = 0; q < 4; ++q) acc[m][n][q] = 0.f;

    const float4* x4 = reinterpret_cast<const float4*>(x);
    const float4* B4 = reinterpret_cast<const float4*>(Bm);

    for (int kc = 0; kc < 2; ++kc) {
        if (kc) __syncthreads();
        // Stage x chunk: 128 t x 16 float4, tf32 hi/lo split
#pragma unroll
        for (int i = 0; i < 8; ++i) {
            int f  = tid + 256 * i;
            int t  = f >> 4;
            int jq = f & 15;
            float4 v = x4[(b * TT + t0 + t) * 32 + kc * 16 + jq];
            float4 hv, lv;
            hv.x = __uint_as_float(tf32bits(v.x)); lv.x = v.x - hv.x;
            hv.y = __uint_as_float(tf32bits(v.y)); lv.y = v.y - hv.y;
            hv.z = __uint_as_float(tf32bits(v.z)); lv.z = v.z - hv.z;
            hv.w = __uint_as_float(tf32bits(v.w)); lv.w = v.w - hv.w;
            *reinterpret_cast<float4*>(&xhi[t * KST + jq * 4]) = hv;
            *reinterpret_cast<float4*>(&xlo[t * KST + jq * 4]) = lv;
        }
        // Stage B chunk: 64 h x 16 float4
#pragma unroll
        for (int i = 0; i < 4; ++i) {
            int f  = tid + 256 * i;
            int h  = f >> 4;
            int jq = f & 15;
            float4 v = B4[h * 32 + kc * 16 + jq];
            float4 hv, lv;
            hv.x = __uint_as_float(tf32bits(v.x)); lv.x = v.x - hv.x;
            hv.y = __uint_as_float(tf32bits(v.y)); lv.y = v.y - hv.y;
            hv.z = __uint_as_float(tf32bits(v.z)); lv.z = v.z - hv.z;
            hv.w = __uint_as_float(tf32bits(v.w)); lv.w = v.w - hv.w;
            *reinterpret_cast<float4*>(&bhi[h * KST + jq * 4]) = hv;
            *reinterpret_cast<float4*>(&blo[h * KST + jq * 4]) = lv;
        }
        __syncthreads();

#pragma unroll
        for (int ks = 0; ks < 8; ++ks) {
            const int j0 = ks * 8;
            unsigned ah[2][4], al[2][4];
#pragma unroll
            for (int m = 0; m < 2; ++m) {
                int base = (wt * 32 + m * 16 + lr) * KST + j0 + lc;
                ah[m][0] = fbits(xhi[base]);
                ah[m][1] = fbits(xhi[base + 8 * KST]);
                ah[m][2] = fbits(xhi[base + 4]);
                ah[m][3] = fbits(xhi[base + 8 * KST + 4]);
                al[m][0] = fbits(xlo[base]);
                al[m][1] = fbits(xlo[base + 8 * KST]);
                al[m][2] = fbits(xlo[base + 4]);
                al[m][3] = fbits(xlo[base + 8 * KST + 4]);
            }
#pragma unroll
            for (int n = 0; n < 4; ++n) {
                int hb = (wh * 32 + n * 8 + lr) * KST + j0 + lc;
                unsigned bh0 = fbits(bhi[hb]);
                unsigned bh1 = fbits(bhi[hb + 4]);
                unsigned bl0 = fbits(blo[hb]);
                unsigned bl1 = fbits(blo[hb + 4]);
#pragma unroll
                for (int m = 0; m < 2; ++m) {
                    mma_tf32(acc[m][n][0], acc[m][n][1], acc[m][n][2], acc[m][n][3],
                             ah[m][0], ah[m][1], ah[m][2], ah[m][3], bh0, bh1);
                    mma_tf32(acc[m][n][0], acc[m][n][1], acc[m][n][2], acc[m][n][3],
                             ah[m][0], ah[m][1], ah[m][2], ah[m][3], bl0, bl1);
                    mma_tf32(acc[m][n][0], acc[m][n][1], acc[m][n][2], acc[m][n][3],
                             al[m][0], al[m][1], al[m][2], al[m][3], bh0, bh1);
                }
            }
        }
    }
    __syncthreads();

    // Stage D = Bx into smem as [t][h], stride 65 (aliases staging region).
    float* sD = sm;
#pragma unroll
    for (int m = 0; m < 2; ++m)
#pragma unroll
        for (int n = 0; n < 4; ++n) {
            int tr = wt * 32 + m * 16 + lr;
            int hc = wh * 32 + n * 8 + 2 * lc;
            sD[tr * 65 + hc]           = acc[m][n][0];
            sD[tr * 65 + hc + 1]       = acc[m][n][1];
            sD[(tr + 8) * 65 + hc]     = acc[m][n][2];
            sD[(tr + 8) * 65 + hc + 1] = acc[m][n][3];
        }
    __syncthreads();

    // ---- Segment-local scan ----
    const int h = tid & 63;
    const int c = tid >> 6;             // 0..3: 32-step chunk

    const float mag = expf(-expf(nu[h]));
    float sn, cs;
    sincosf(theta[h], &sn, &cs);
    const float Lr = mag * cs;
    const float Li = mag * sn;

    // P = lam^32 (all threads; needed for phase C adjustment too)
    float Pr = Lr, Pi = Li;
#pragma unroll
    for (int s = 0; s < 5; ++s) {
        float nr = Pr * Pr - Pi * Pi;
        float ni = 2.f * Pr * Pi;
        Pr = nr; Pi = ni;
    }

    float u[32];
#pragma unroll
    for (int k = 0; k < 32; ++k) u[k] = sD[(c * 32 + k) * 65 + h];

    // Phase A: local chunk scan from zero -> chunk value V
    float yr = 0.f, yi = 0.f;
#pragma unroll
    for (int k = 0; k < 32; ++k) {
        float nyr = fmaf(Lr, yr, fmaf(-Li, yi, u[k]));
        float nyi = fmaf(Lr, yi, Li * yr);
        yr = nyr; yi = nyi;
    }
    Vr_s[c * 64 + h] = yr;
    Vi_s[c * 64 + h] = yi;
    __syncthreads();

    // Combine (tid<64): chunk prefixes from zero, segment carry, LOOKBACK.
    if (tid < 64) {
        float wr = 0.f, wi = 0.f;
        Wr_s[h] = 0.f; Wi_s[h] = 0.f;
#pragma unroll
        for (int cc = 1; cc < 4; ++cc) {
            float vr = Vr_s[(cc - 1) * 64 + h];
            float vi = Vi_s[(cc - 1) * 64 + h];
            float nwr = vr + (Pr * wr - Pi * wi);
            float nwi = vi + (Pr * wi + Pi * wr);
            wr = nwr; wi = nwi;
            Wr_s[cc * 64 + h] = wr;
            Wi_s[cc * 64 + h] = wi;
        }
        float vr = Vr_s[3 * 64 + h];
        float vi = Vi_s[3 * 64 + h];
        float Cr = vr + (Pr * wr - Pi * wi);   // segment carry from zero
        float Ci = vi + (Pr * wi + Pi * wr);

        // Q = lam^128 = P^4
        float Q2r = Pr * Pr - Pi * Pi;
        float Q2i = 2.f * Pr * Pi;
        float Qr = Q2r * Q2r - Q2i * Q2i;
        float Qi = 2.f * Q2r * Q2i;

        // Incoming state S = E_{ts-1} (lookback) or 1 for ts == 0.
        float Sr = 1.f, Si = 0.f;
        if (ts > 0) {
            const unsigned* fp = &g_flag[b * 8 + ts - 1];
            unsigned f;
            do {
                asm volatile("ld.acquire.gpu.b32 %0, [%1];"
                             : "=r"(f) : "l"(fp) : "memory");
            } while (f == 0u);
            float2 e = g_C[(b * 8 + ts - 1) * 64 + h];
            Sr = e.x; Si = e.y;
        }
        // Publish inclusive state E_ts = Q * S + C
        float Er = Qr * Sr - Qi * Si + Cr;
        float Ei = Qr * Si + Qi * Sr + Ci;
        g_C[(b * 8 + ts) * 64 + h] = make_float2(Er, Ei);
        __threadfence();
        Ssr[h] = Sr; Ssi[h] = Si;
    }
    __syncthreads();
    if (tid == 0) {
        asm volatile("st.release.gpu.b32 [%0], %1;"
                     :: "l"(&g_flag[b * 8 + ts]), "r"(1u) : "memory");
    }

    // Phase C: incoming state for chunk c = W_c + P^c * S ; write final out.
    {
        float Sr = Ssr[h], Si = Ssi[h];
        // pc = P^c  (c in 0..3)
        float pcr = 1.f, pci = 0.f;
#pragma unroll
        for (int d = 0; d < 2; ++d) {
            if ((c >> d) & 1) {
                float br = (d == 0) ? Pr : (Pr * Pr - Pi * Pi);
                float bi = (d == 0) ? Pi : (2.f * Pr * Pi);
                float nr = pcr * br - pci * bi;
                float ni = pcr * bi + pci * br;
                pcr = nr; pci = ni;
            }
        }
        yr = Wr_s[c * 64 + h] + (pcr * Sr - pci * Si);
        yi = Wi_s[c * 64 + h] + (pcr * Si + pci * Sr);
    }
    float* op = out + (b * TT + t0 + c * 32) * (2 * HH) + h;
#pragma unroll
    for (int k = 0; k < 32; ++k) {
        float nyr = fmaf(Lr, yr, fmaf(-Li, yi, u[k]));
        float nyi = fmaf(Lr, yi, Li * yr);
        yr = nyr; yi = nyi;
        op[k * 128]      = yr;   // re at [b,t,h]
        op[k * 128 + 64] = yi;   // im at [b,t,H+h]
    }
}

// ---------------------------------------------------------------------------
extern "C" void kernel_launch(void* const* d_in, const int* in_sizes, int n_in,
                              void* d_out, int out_size) {
    const float* x     = (const float*)d_in[0];   // [16,1024,128]
    const float* Bm    = (const float*)d_in[1];   // [64,128]
    const float* nu    = (const float*)d_in[2];   // [64]
    const float* theta = (const float*)d_in[3];   // [64]
    float* out = (float*)d_out;                   // [16,1024,128]

    cudaFuncSetAttribute(fused_kernel,
                         cudaFuncAttributeMaxDynamicSharedMemorySize,
                         K1_SMEM_BYTES);
    reset_kernel<<<1, 128>>>();
    fused_kernel<<<128, 256, K1_SMEM_BYTES>>>(x, Bm, nu, theta, out);
}

// round 7
// speedup vs baseline: 1.0627x; 1.0627x over previous
#include <cuda_runtime.h>
#include <math.h>

#define BB 16      // batch
#define TT 1024    // sequence
#define JJ 128     // input dim
#define HH 64      // hidden (complex) dim

// Per-(b, segment) ZERO-STATE carry C (complex, 64 h) + ready flags.
// Published unconditionally by every block -> no serial chain (decoupled).
__device__ __align__(16) float2 g_C[BB * 8 * HH];
__device__ unsigned g_flag[BB * 8];

// ---------------------------------------------------------------------------
// tf32 helpers
// ---------------------------------------------------------------------------
__device__ __forceinline__ unsigned tf32bits(float v) {
    unsigned r;
    asm("cvt.rna.tf32.f32 %0, %1;" : "=r"(r) : "f"(v));
    return r;
}
__device__ __forceinline__ void mma_tf32(float& d0, float& d1, float& d2, float& d3,
                                         unsigned a0, unsigned a1, unsigned a2, unsigned a3,
                                         unsigned b0, unsigned b1) {
    asm("mma.sync.aligned.m16n8k8.row.col.f32.tf32.tf32.f32 "
        "{%0,%1,%2,%3}, {%4,%5,%6,%7}, {%8,%9}, {%0,%1,%2,%3};"
        : "+f"(d0), "+f"(d1), "+f"(d2), "+f"(d3)
        : "r"(a0), "r"(a1), "r"(a2), "r"(a3), "r"(b0), "r"(b1));
}
__device__ __forceinline__ unsigned fbits(float v) { return __float_as_uint(v); }

// ---------------------------------------------------------------------------
// Prologue: reset lookback flags (graph-replay safe).
// ---------------------------------------------------------------------------
__global__ void reset_kernel() { g_flag[threadIdx.x] = 0u; }

// ---------------------------------------------------------------------------
// K1: fused GEMM (3xTF32) + segment scan with DECOUPLED lookback.
// Grid 128 = 16 b x 8 t-segments (128 t each), 256 threads, ALL RESIDENT
// (single wave). Each block publishes its zero-state carry immediately;
// consumers combine predecessor carries locally (no serial chain).
// ---------------------------------------------------------------------------
#define KST 68
#define K1_SMEM_BYTES (384 * KST * 4)   // xhi(128)+xlo(128)+bhi(64)+blo(64) rows

__global__ __launch_bounds__(256) void fused_kernel(const float* __restrict__ x,
                                                    const float* __restrict__ Bm,
                                                    const float* __restrict__ nu,
                                                    const float* __restrict__ theta,
                                                    float* __restrict__ out) {
    extern __shared__ __align__(16) float sm[];
    float* xhi = sm;                    // [t 0..127][j 0..63] stride 68
    float* xlo = sm + 128 * KST;
    float* bhi = sm + 256 * KST;        // [h 0..63][j 0..63] stride 68
    float* blo = sm + 320 * KST;

    __shared__ float Vr_s[4 * 64], Vi_s[4 * 64];
    __shared__ float Wr_s[4 * 64], Wi_s[4 * 64];
    __shared__ float Ssr[64], Ssi[64];      // incoming segment state S

    const int tid  = threadIdx.x;
    const int lane = tid & 31;
    const int wid  = tid >> 5;
    const int wt   = wid >> 1;          // 0..3 -> 32 t
    const int wh   = wid & 1;           // 0..1 -> 32 h
    const int b    = blockIdx.x >> 3;
    const int ts   = blockIdx.x & 7;
    const int t0   = ts * 128;
    const int lr   = lane >> 2;         // 0..7
    const int lc   = lane & 3;          // 0..3

    float acc[2][4][4];
#pragma unroll
    for (int m = 0; m < 2; ++m)
#pragma unroll
        for (int n = 0; n < 4; ++n)
#pragma unroll
            for (int q = 0; q < 4; ++q) acc[m][n][q] = 0.f;

    const float4* x4 = reinterpret_cast<const float4*>(x);
    const float4* B4 = reinterpret_cast<const float4*>(Bm);

    for (int kc = 0; kc < 2; ++kc) {
        if (kc) __syncthreads();
        // Stage x chunk: 128 t x 16 float4, tf32 hi/lo split
#pragma unroll
        for (int i = 0; i < 8; ++i) {
            int f  = tid + 256 * i;
            int t  = f >> 4;
            int jq = f & 15;
            float4 v = x4[(b * TT + t0 + t) * 32 + kc * 16 + jq];
            float4 hv, lv;
            hv.x = __uint_as_float(tf32bits(v.x)); lv.x = v.x - hv.x;
            hv.y = __uint_as_float(tf32bits(v.y)); lv.y = v.y - hv.y;
            hv.z = __uint_as_float(tf32bits(v.z)); lv.z = v.z - hv.z;
            hv.w = __uint_as_float(tf32bits(v.w)); lv.w = v.w - hv.w;
            *reinterpret_cast<float4*>(&xhi[t * KST + jq * 4]) = hv;
            *reinterpret_cast<float4*>(&xlo[t * KST + jq * 4]) = lv;
        }
        // Stage B chunk: 64 h x 16 float4
#pragma unroll
        for (int i = 0; i < 4; ++i) {
            int f  = tid + 256 * i;
            int h  = f >> 4;
            int jq = f & 15;
            float4 v = B4[h * 32 + kc * 16 + jq];
            float4 hv, lv;
            hv.x = __uint_as_float(tf32bits(v.x)); lv.x = v.x - hv.x;
            hv.y = __uint_as_float(tf32bits(v.y)); lv.y = v.y - hv.y;
            hv.z = __uint_as_float(tf32bits(v.z)); lv.z = v.z - hv.z;
            hv.w = __uint_as_float(tf32bits(v.w)); lv.w = v.w - hv.w;
            *reinterpret_cast<float4*>(&bhi[h * KST + jq * 4]) = hv;
            *reinterpret_cast<float4*>(&blo[h * KST + jq * 4]) = lv;
        }
        __syncthreads();

#pragma unroll
        for (int ks = 0; ks < 8; ++ks) {
            const int j0 = ks * 8;
            unsigned ah[2][4], al[2][4];
#pragma unroll
            for (int m = 0; m < 2; ++m) {
                int base = (wt * 32 + m * 16 + lr) * KST + j0 + lc;
                ah[m][0] = fbits(xhi[base]);
                ah[m][1] = fbits(xhi[base + 8 * KST]);
                ah[m][2] = fbits(xhi[base + 4]);
                ah[m][3] = fbits(xhi[base + 8 * KST + 4]);
                al[m][0] = fbits(xlo[base]);
                al[m][1] = fbits(xlo[base + 8 * KST]);
                al[m][2] = fbits(xlo[base + 4]);
                al[m][3] = fbits(xlo[base + 8 * KST + 4]);
            }
#pragma unroll
            for (int n = 0; n < 4; ++n) {
                int hb = (wh * 32 + n * 8 + lr) * KST + j0 + lc;
                unsigned bh0 = fbits(bhi[hb]);
                unsigned bh1 = fbits(bhi[hb + 4]);
                unsigned bl0 = fbits(blo[hb]);
                unsigned bl1 = fbits(blo[hb + 4]);
#pragma unroll
                for (int m = 0; m < 2; ++m) {
                    mma_tf32(acc[m][n][0], acc[m][n][1], acc[m][n][2], acc[m][n][3],
                             ah[m][0], ah[m][1], ah[m][2], ah[m][3], bh0, bh1);
                    mma_tf32(acc[m][n][0], acc[m][n][1], acc[m][n][2], acc[m][n][3],
                             ah[m][0], ah[m][1], ah[m][2], ah[m][3], bl0, bl1);
                    mma_tf32(acc[m][n][0], acc[m][n][1], acc[m][n][2], acc[m][n][3],
                             al[m][0], al[m][1], al[m][2], al[m][3], bh0, bh1);
                }
            }
        }
    }
    __syncthreads();

    // Stage D = Bx into smem as [t][h], stride 65 (aliases staging region).
    float* sD = sm;
#pragma unroll
    for (int m = 0; m < 2; ++m)
#pragma unroll
        for (int n = 0; n < 4; ++n) {
            int tr = wt * 32 + m * 16 + lr;
            int hc = wh * 32 + n * 8 + 2 * lc;
            sD[tr * 65 + hc]           = acc[m][n][0];
            sD[tr * 65 + hc + 1]       = acc[m][n][1];
            sD[(tr + 8) * 65 + hc]     = acc[m][n][2];
            sD[(tr + 8) * 65 + hc + 1] = acc[m][n][3];
        }
    __syncthreads();

    // ---- Segment-local scan ----
    const int h = tid & 63;
    const int c = tid >> 6;             // 0..3: 32-step chunk

    const float mag = expf(-expf(nu[h]));
    float sn, cs;
    sincosf(theta[h], &sn, &cs);
    const float Lr = mag * cs;
    const float Li = mag * sn;

    // P = lam^32
    float Pr = Lr, Pi = Li;
#pragma unroll
    for (int s = 0; s < 5; ++s) {
        float nr = Pr * Pr - Pi * Pi;
        float ni = 2.f * Pr * Pi;
        Pr = nr; Pi = ni;
    }

    float u[32];
#pragma unroll
    for (int k = 0; k < 32; ++k) u[k] = sD[(c * 32 + k) * 65 + h];

    // Phase A: local chunk scan from zero -> chunk value V
    float yr = 0.f, yi = 0.f;
#pragma unroll
    for (int k = 0; k < 32; ++k) {
        float nyr = fmaf(Lr, yr, fmaf(-Li, yi, u[k]));
        float nyi = fmaf(Lr, yi, Li * yr);
        yr = nyr; yi = nyi;
    }
    Vr_s[c * 64 + h] = yr;
    Vi_s[c * 64 + h] = yi;
    __syncthreads();

    // Combine (tid<64): chunk prefixes + ZERO-STATE segment carry C; publish.
    if (tid < 64) {
        float wr = 0.f, wi = 0.f;
        Wr_s[h] = 0.f; Wi_s[h] = 0.f;
#pragma unroll
        for (int cc = 1; cc < 4; ++cc) {
            float vr = Vr_s[(cc - 1) * 64 + h];
            float vi = Vi_s[(cc - 1) * 64 + h];
            float nwr = vr + (Pr * wr - Pi * wi);
            float nwi = vi + (Pr * wi + Pi * wr);
            wr = nwr; wi = nwi;
            Wr_s[cc * 64 + h] = wr;
            Wi_s[cc * 64 + h] = wi;
        }
        float vr = Vr_s[3 * 64 + h];
        float vi = Vi_s[3 * 64 + h];
        float Cr = vr + (Pr * wr - Pi * wi);   // segment carry from zero state
        float Ci = vi + (Pr * wi + Pi * wr);
        g_C[(b * 8 + ts) * 64 + h] = make_float2(Cr, Ci);
        __threadfence();
    }
    __syncthreads();
    if (tid == 0) {
        asm volatile("st.release.gpu.b32 [%0], %1;"
                     :: "l"(&g_flag[b * 8 + ts]), "r"(1u) : "memory");
    }

    // Decoupled lookback (tid<64): S = 1; for g<ts: S = Q*S + C_g  (Horner).
    // All predecessor carries publish in parallel -> no serial chain.
    if (tid < 64) {
        // Q = lam^128 = P^4
        float Q2r = Pr * Pr - Pi * Pi;
        float Q2i = 2.f * Pr * Pi;
        float Qr = Q2r * Q2r - Q2i * Q2i;
        float Qi = 2.f * Q2r * Q2i;

        float Sr = 1.f, Si = 0.f;
        for (int g = 0; g < ts; ++g) {
            const unsigned* fp = &g_flag[b * 8 + g];
            unsigned f;
            do {
                asm volatile("ld.acquire.gpu.b32 %0, [%1];"
                             : "=r"(f) : "l"(fp) : "memory");
            } while (f == 0u);
            float2 cg = g_C[(b * 8 + g) * 64 + h];
            float nr = Qr * Sr - Qi * Si + cg.x;
            float ni = Qr * Si + Qi * Sr + cg.y;
            Sr = nr; Si = ni;
        }
        Ssr[h] = Sr; Ssi[h] = Si;
    }
    __syncthreads();

    // Phase C: incoming state for chunk c = W_c + P^c * S ; write final out.
    {
        float Sr = Ssr[h], Si = Ssi[h];
        float pcr = 1.f, pci = 0.f;
#pragma unroll
        for (int d = 0; d < 2; ++d) {
            if ((c >> d) & 1) {
                float br = (d == 0) ? Pr : (Pr * Pr - Pi * Pi);
                float bi = (d == 0) ? Pi : (2.f * Pr * Pi);
                float nr = pcr * br - pci * bi;
                float ni = pcr * bi + pci * br;
                pcr = nr; pci = ni;
            }
        }
        yr = Wr_s[c * 64 + h] + (pcr * Sr - pci * Si);
        yi = Wi_s[c * 64 + h] + (pcr * Si + pci * Sr);
    }
    float* op = out + (b * TT + t0 + c * 32) * (2 * HH) + h;
#pragma unroll
    for (int k = 0; k < 32; ++k) {
        float nyr = fmaf(Lr, yr, fmaf(-Li, yi, u[k]));
        float nyi = fmaf(Lr, yi, Li * yr);
        yr = nyr; yi = nyi;
        op[k * 128]      = yr;   // re at [b,t,h]
        op[k * 128 + 64] = yi;   // im at [b,t,H+h]
    }
}

// ---------------------------------------------------------------------------
extern "C" void kernel_launch(void* const* d_in, const int* in_sizes, int n_in,
                              void* d_out, int out_size) {
    const float* x     = (const float*)d_in[0];   // [16,1024,128]
    const float* Bm    = (const float*)d_in[1];   // [64,128]
    const float* nu    = (const float*)d_in[2];   // [64]
    const float* theta = (const float*)d_in[3];   // [64]
    float* out = (float*)d_out;                   // [16,1024,128]

    cudaFuncSetAttribute(fused_kernel,
                         cudaFuncAttributeMaxDynamicSharedMemorySize,
                         K1_SMEM_BYTES);
    reset_kernel<<<1, 128>>>();
    fused_kernel<<<128, 256, K1_SMEM_BYTES>>>(x, Bm, nu, theta, out);
}

// round 8
// speedup vs baseline: 1.2889x; 1.2128x over previous
#include <cuda_runtime.h>
#include <math.h>

#define BB 16      // batch
#define TT 1024    // sequence
#define JJ 128     // input dim
#define HH 64      // hidden (complex) dim

// Per-(b, segment) ZERO-STATE carry C (complex, 64 h).
__device__ __align__(16) float2 g_C[BB * 8 * HH];
// lam^k table, k = 1..128:  g_L[(k-1)*64 + h]
__device__ __align__(16) float2 g_L[128 * HH];

// ---------------------------------------------------------------------------
// tf32 helpers
// ---------------------------------------------------------------------------
__device__ __forceinline__ unsigned tf32bits(float v) {
    unsigned r;
    asm("cvt.rna.tf32.f32 %0, %1;" : "=r"(r) : "f"(v));
    return r;
}
__device__ __forceinline__ void mma_tf32(float& d0, float& d1, float& d2, float& d3,
                                         unsigned a0, unsigned a1, unsigned a2, unsigned a3,
                                         unsigned b0, unsigned b1) {
    asm("mma.sync.aligned.m16n8k8.row.col.f32.tf32.tf32.f32 "
        "{%0,%1,%2,%3}, {%4,%5,%6,%7}, {%8,%9}, {%0,%1,%2,%3};"
        : "+f"(d0), "+f"(d1), "+f"(d2), "+f"(d3)
        : "r"(a0), "r"(a1), "r"(a2), "r"(a3), "r"(b0), "r"(b1));
}
__device__ __forceinline__ unsigned fbits(float v) { return __float_as_uint(v); }

// ---------------------------------------------------------------------------
// K1: fused GEMM (3xTF32) + zero-state segment scan (round-5 structure).
// Grid 128 = 16 b x 8 t-segments (128 t each), 256 threads.
// Publishes zero-state carry C to g_C; b==0 blocks also fill the lam^k table.
// NO cross-block waiting — K2 applies the cross-segment correction.
// ---------------------------------------------------------------------------
#define KST 68
#define K1_SMEM_BYTES (384 * KST * 4)   // xhi(128)+xlo(128)+bhi(64)+blo(64) rows

__global__ __launch_bounds__(256) void fused_kernel(const float* __restrict__ x,
                                                    const float* __restrict__ Bm,
                                                    const float* __restrict__ nu,
                                                    const float* __restrict__ theta,
                                                    float* __restrict__ out) {
    extern __shared__ __align__(16) float sm[];
    float* xhi = sm;                    // [t 0..127][j 0..63] stride 68
    float* xlo = sm + 128 * KST;
    float* bhi = sm + 256 * KST;        // [h 0..63][j 0..63] stride 68
    float* blo = sm + 320 * KST;

    __shared__ float Vr_s[4 * 64], Vi_s[4 * 64];
    __shared__ float Wr_s[4 * 64], Wi_s[4 * 64];

    const int tid  = threadIdx.x;
    const int lane = tid & 31;
    const int wid  = tid >> 5;
    const int wt   = wid >> 1;          // 0..3 -> 32 t
    const int wh   = wid & 1;           // 0..1 -> 32 h
    const int b    = blockIdx.x >> 3;
    const int ts   = blockIdx.x & 7;
    const int t0   = ts * 128;
    const int lr   = lane >> 2;         // 0..7
    const int lc   = lane & 3;          // 0..3

    float acc[2][4][4];
#pragma unroll
    for (int m = 0; m < 2; ++m)
#pragma unroll
        for (int n = 0; n < 4; ++n)
#pragma unroll
            for (int q = 0; q < 4; ++q) acc[m][n][q] = 0.f;

    const float4* x4 = reinterpret_cast<const float4*>(x);
    const float4* B4 = reinterpret_cast<const float4*>(Bm);

    for (int kc = 0; kc < 2; ++kc) {
        if (kc) __syncthreads();
        // Stage x chunk: 128 t x 16 float4, tf32 hi/lo split
#pragma unroll
        for (int i = 0; i < 8; ++i) {
            int f  = tid + 256 * i;
            int t  = f >> 4;
            int jq = f & 15;
            float4 v = x4[(b * TT + t0 + t) * 32 + kc * 16 + jq];
            float4 hv, lv;
            hv.x = __uint_as_float(tf32bits(v.x)); lv.x = v.x - hv.x;
            hv.y = __uint_as_float(tf32bits(v.y)); lv.y = v.y - hv.y;
            hv.z = __uint_as_float(tf32bits(v.z)); lv.z = v.z - hv.z;
            hv.w = __uint_as_float(tf32bits(v.w)); lv.w = v.w - hv.w;
            *reinterpret_cast<float4*>(&xhi[t * KST + jq * 4]) = hv;
            *reinterpret_cast<float4*>(&xlo[t * KST + jq * 4]) = lv;
        }
        // Stage B chunk: 64 h x 16 float4
#pragma unroll
        for (int i = 0; i < 4; ++i) {
            int f  = tid + 256 * i;
            int h  = f >> 4;
            int jq = f & 15;
            float4 v = B4[h * 32 + kc * 16 + jq];
            float4 hv, lv;
            hv.x = __uint_as_float(tf32bits(v.x)); lv.x = v.x - hv.x;
            hv.y = __uint_as_float(tf32bits(v.y)); lv.y = v.y - hv.y;
            hv.z = __uint_as_float(tf32bits(v.z)); lv.z = v.z - hv.z;
            hv.w = __uint_as_float(tf32bits(v.w)); lv.w = v.w - hv.w;
            *reinterpret_cast<float4*>(&bhi[h * KST + jq * 4]) = hv;
            *reinterpret_cast<float4*>(&blo[h * KST + jq * 4]) = lv;
        }
        __syncthreads();

#pragma unroll
        for (int ks = 0; ks < 8; ++ks) {
            const int j0 = ks * 8;
            unsigned ah[2][4], al[2][4];
#pragma unroll
            for (int m = 0; m < 2; ++m) {
                int base = (wt * 32 + m * 16 + lr) * KST + j0 + lc;
                ah[m][0] = fbits(xhi[base]);
                ah[m][1] = fbits(xhi[base + 8 * KST]);
                ah[m][2] = fbits(xhi[base + 4]);
                ah[m][3] = fbits(xhi[base + 8 * KST + 4]);
                al[m][0] = fbits(xlo[base]);
                al[m][1] = fbits(xlo[base + 8 * KST]);
                al[m][2] = fbits(xlo[base + 4]);
                al[m][3] = fbits(xlo[base + 8 * KST + 4]);
            }
#pragma unroll
            for (int n = 0; n < 4; ++n) {
                int hb = (wh * 32 + n * 8 + lr) * KST + j0 + lc;
                unsigned bh0 = fbits(bhi[hb]);
                unsigned bh1 = fbits(bhi[hb + 4]);
                unsigned bl0 = fbits(blo[hb]);
                unsigned bl1 = fbits(blo[hb + 4]);
#pragma unroll
                for (int m = 0; m < 2; ++m) {
                    mma_tf32(acc[m][n][0], acc[m][n][1], acc[m][n][2], acc[m][n][3],
                             ah[m][0], ah[m][1], ah[m][2], ah[m][3], bh0, bh1);
                    mma_tf32(acc[m][n][0], acc[m][n][1], acc[m][n][2], acc[m][n][3],
                             ah[m][0], ah[m][1], ah[m][2], ah[m][3], bl0, bl1);
                    mma_tf32(acc[m][n][0], acc[m][n][1], acc[m][n][2], acc[m][n][3],
                             al[m][0], al[m][1], al[m][2], al[m][3], bh0, bh1);
                }
            }
        }
    }
    __syncthreads();

    // Stage D = Bx into smem as [t][h], stride 65 (aliases staging region).
    float* sD = sm;
#pragma unroll
    for (int m = 0; m < 2; ++m)
#pragma unroll
        for (int n = 0; n < 4; ++n) {
            int tr = wt * 32 + m * 16 + lr;
            int hc = wh * 32 + n * 8 + 2 * lc;
            sD[tr * 65 + hc]           = acc[m][n][0];
            sD[tr * 65 + hc + 1]       = acc[m][n][1];
            sD[(tr + 8) * 65 + hc]     = acc[m][n][2];
            sD[(tr + 8) * 65 + hc + 1] = acc[m][n][3];
        }
    __syncthreads();

    // ---- Segment-local scan (zero initial state) ----
    const int h = tid & 63;
    const int c = tid >> 6;             // 0..3: 32-step chunk

    const float mag = expf(-expf(nu[h]));
    float sn, cs;
    sincosf(theta[h], &sn, &cs);
    const float Lr = mag * cs;
    const float Li = mag * sn;

    float u[32];
#pragma unroll
    for (int k = 0; k < 32; ++k) u[k] = sD[(c * 32 + k) * 65 + h];

    // Phase A: local chunk scan from zero -> chunk value V
    float yr = 0.f, yi = 0.f;
#pragma unroll
    for (int k = 0; k < 32; ++k) {
        float nyr = fmaf(Lr, yr, fmaf(-Li, yi, u[k]));
        float nyi = fmaf(Lr, yi, Li * yr);
        yr = nyr; yi = nyi;
    }
    Vr_s[c * 64 + h] = yr;
    Vi_s[c * 64 + h] = yi;
    __syncthreads();

    // Combine (tid<64): P = lam^32; chunk prefixes + segment carry -> g_C.
    if (tid < 64) {
        float Pr = Lr, Pi = Li;
#pragma unroll
        for (int s = 0; s < 5; ++s) {
            float nr = Pr * Pr - Pi * Pi;
            float ni = 2.f * Pr * Pi;
            Pr = nr; Pi = ni;
        }
        float wr = 0.f, wi = 0.f;
        Wr_s[h] = 0.f; Wi_s[h] = 0.f;
#pragma unroll
        for (int cc = 1; cc < 4; ++cc) {
            float vr = Vr_s[(cc - 1) * 64 + h];
            float vi = Vi_s[(cc - 1) * 64 + h];
            float nwr = vr + (Pr * wr - Pi * wi);
            float nwi = vi + (Pr * wi + Pi * wr);
            wr = nwr; wi = nwi;
            Wr_s[cc * 64 + h] = wr;
            Wi_s[cc * 64 + h] = wi;
        }
        float vr = Vr_s[3 * 64 + h];
        float vi = Vi_s[3 * 64 + h];
        float Cr = vr + (Pr * wr - Pi * wi);
        float Ci = vi + (Pr * wi + Pi * wr);
        g_C[(b * 8 + ts) * 64 + h] = make_float2(Cr, Ci);
    }

    // lam^k table fill (b==0 blocks only; k = ts*16+1 .. ts*16+16).
    if (b == 0) {
        int kk = ts * 16 + 1 + (tid >> 6);       // 4 base k values per block
        int hh = tid & 63;
        float enu = expf(nu[hh]);
        float th  = theta[hh];
#pragma unroll
        for (int i = 0; i < 4; ++i) {
            int k2 = kk + i * 4;
            float m2 = expf(-(float)k2 * enu);
            float s2, c2;
            sincosf((float)k2 * th, &s2, &c2);
            g_L[(k2 - 1) * 64 + hh] = make_float2(m2 * c2, m2 * s2);
        }
    }
    __syncthreads();

    // Phase C: zero-state outputs (K2 adds the cross-segment correction).
    yr = Wr_s[c * 64 + h];
    yi = Wi_s[c * 64 + h];
    float* op = out + (b * TT + t0 + c * 32) * (2 * HH) + h;
#pragma unroll
    for (int k = 0; k < 32; ++k) {
        float nyr = fmaf(Lr, yr, fmaf(-Li, yi, u[k]));
        float nyi = fmaf(Lr, yi, Li * yr);
        yr = nyr; yi = nyi;
        op[k * 128]      = yr;   // re at [b,t,h]
        op[k * 128 + 64] = yi;   // im at [b,t,H+h]
    }
}

// ---------------------------------------------------------------------------
// K2: out[b,t,h] += lam_h^(tl+1) * S(b,seg,h),  S = Horner over carries.
// One (t, 4h) item per thread. 1024 blocks x 256 threads; table-driven
// lam powers (no MUFU, no serial chains) -> pure bandwidth.
// ---------------------------------------------------------------------------
__global__ __launch_bounds__(256) void fixup_kernel(float* __restrict__ out) {
    const int tid = threadIdx.x;
    const int bx  = blockIdx.x;
    const int b   = bx >> 6;            // 0..15
    const int tb  = bx & 63;            // 64 blocks of 16 t each
    const int t   = tb * 16 + (tid >> 4);
    const int hq  = tid & 15;
    const int h0  = hq * 4;
    const int seg = t >> 7;
    const int k   = (t & 127) + 1;      // 1..128

    // lam^k for 4 h (table, L2-hot)
    const float4* Lp = reinterpret_cast<const float4*>(&g_L[(k - 1) * 64 + h0]);
    float4 l01 = Lp[0];                 // (re,im) h0, h0+1
    float4 l23 = Lp[1];
    float lkr[4] = {l01.x, l01.z, l23.x, l23.z};
    float lki[4] = {l01.y, l01.w, l23.y, l23.w};

    // S = Q^seg + sum Q^(seg-1-g) C_g  via Horner; Q = lam^128 (table row 127)
    float Sr[4] = {1.f, 1.f, 1.f, 1.f};
    float Si[4] = {0.f, 0.f, 0.f, 0.f};
    if (seg > 0) {
        const float4* Qp = reinterpret_cast<const float4*>(&g_L[127 * 64 + h0]);
        float4 q01 = Qp[0];
        float4 q23 = Qp[1];
        float Qr[4] = {q01.x, q01.z, q23.x, q23.z};
        float Qi[4] = {q01.y, q01.w, q23.y, q23.w};
        for (int g = 0; g < seg; ++g) {
            const float4* Cp =
                reinterpret_cast<const float4*>(&g_C[(b * 8 + g) * 64 + h0]);
            float4 c01 = Cp[0];
            float4 c23 = Cp[1];
            float cr[4] = {c01.x, c01.z, c23.x, c23.z};
            float ci[4] = {c01.y, c01.w, c23.y, c23.w};
#pragma unroll
            for (int q = 0; q < 4; ++q) {
                float nr = Qr[q] * Sr[q] - Qi[q] * Si[q] + cr[q];
                float ni = Qr[q] * Si[q] + Qi[q] * Sr[q] + ci[q];
                Sr[q] = nr; Si[q] = ni;
            }
        }
    }

    // z = lam^k * S ; out += z
    float zr[4], zi[4];
#pragma unroll
    for (int q = 0; q < 4; ++q) {
        zr[q] = lkr[q] * Sr[q] - lki[q] * Si[q];
        zi[q] = lkr[q] * Si[q] + lki[q] * Sr[q];
    }
    float* p = out + (b * TT + t) * (2 * HH) + h0;
    float4 re = *reinterpret_cast<float4*>(p);
    float4 im = *reinterpret_cast<float4*>(p + 64);
    re.x += zr[0]; re.y += zr[1]; re.z += zr[2]; re.w += zr[3];
    im.x += zi[0]; im.y += zi[1]; im.z += zi[2]; im.w += zi[3];
    *reinterpret_cast<float4*>(p)      = re;
    *reinterpret_cast<float4*>(p + 64) = im;
}

// ---------------------------------------------------------------------------
extern "C" void kernel_launch(void* const* d_in, const int* in_sizes, int n_in,
                              void* d_out, int out_size) {
    const float* x     = (const float*)d_in[0];   // [16,1024,128]
    const float* Bm    = (const float*)d_in[1];   // [64,128]
    const float* nu    = (const float*)d_in[2];   // [64]
    const float* theta = (const float*)d_in[3];   // [64]
    float* out = (float*)d_out;                   // [16,1024,128]

    cudaFuncSetAttribute(fused_kernel,
                         cudaFuncAttributeMaxDynamicSharedMemorySize,
                         K1_SMEM_BYTES);
    fused_kernel<<<128, 256, K1_SMEM_BYTES>>>(x, Bm, nu, theta, out);
    fixup_kernel<<<1024, 256>>>(out);
}

// round 9
// speedup vs baseline: 1.2910x; 1.0017x over previous
#include <cuda_runtime.h>
#include <math.h>

#define BB 16      // batch
#define TT 1024    // sequence
#define JJ 128     // input dim
#define HH 64      // hidden (complex) dim

// Per-(b, segment) ZERO-STATE carry C (complex, 64 h).
__device__ __align__(16) float2 g_C[BB * 8 * HH];
// lam^k table, k = 1..128:  g_L[(k-1)*64 + h]
__device__ __align__(16) float2 g_L[128 * HH];
// Incoming segment state S per (b, seg, h).
__device__ __align__(16) float2 g_S[BB * 8 * HH];

// ---------------------------------------------------------------------------
// tf32 helpers
// ---------------------------------------------------------------------------
__device__ __forceinline__ unsigned tf32bits(float v) {
    unsigned r;
    asm("cvt.rna.tf32.f32 %0, %1;" : "=r"(r) : "f"(v));
    return r;
}
__device__ __forceinline__ void mma_tf32(float& d0, float& d1, float& d2, float& d3,
                                         unsigned a0, unsigned a1, unsigned a2, unsigned a3,
                                         unsigned b0, unsigned b1) {
    asm("mma.sync.aligned.m16n8k8.row.col.f32.tf32.tf32.f32 "
        "{%0,%1,%2,%3}, {%4,%5,%6,%7}, {%8,%9}, {%0,%1,%2,%3};"
        : "+f"(d0), "+f"(d1), "+f"(d2), "+f"(d3)
        : "r"(a0), "r"(a1), "r"(a2), "r"(a3), "r"(b0), "r"(b1));
}
__device__ __forceinline__ unsigned fbits(float v) { return __float_as_uint(v); }

// ---------------------------------------------------------------------------
// K1: fused GEMM (3xTF32) + zero-state segment scan (round-5 form, 7.7us).
// Grid 128 = 16 b x 8 t-segments (128 t each), 256 threads.
// ---------------------------------------------------------------------------
#define KST 68
#define K1_SMEM_BYTES (384 * KST * 4)   // xhi(128)+xlo(128)+bhi(64)+blo(64) rows

__global__ __launch_bounds__(256) void fused_kernel(const float* __restrict__ x,
                                                    const float* __restrict__ Bm,
                                                    const float* __restrict__ nu,
                                                    const float* __restrict__ theta,
                                                    float* __restrict__ out) {
    extern __shared__ __align__(16) float sm[];
    float* xhi = sm;                    // [t 0..127][j 0..63] stride 68
    float* xlo = sm + 128 * KST;
    float* bhi = sm + 256 * KST;        // [h 0..63][j 0..63] stride 68
    float* blo = sm + 320 * KST;

    __shared__ float Vr_s[4 * 64], Vi_s[4 * 64];
    __shared__ float Wr_s[4 * 64], Wi_s[4 * 64];

    const int tid  = threadIdx.x;
    const int lane = tid & 31;
    const int wid  = tid >> 5;
    const int wt   = wid >> 1;          // 0..3 -> 32 t
    const int wh   = wid & 1;           // 0..1 -> 32 h
    const int b    = blockIdx.x >> 3;
    const int ts   = blockIdx.x & 7;
    const int t0   = ts * 128;
    const int lr   = lane >> 2;         // 0..7
    const int lc   = lane & 3;          // 0..3

    float acc[2][4][4];
#pragma unroll
    for (int m = 0; m < 2; ++m)
#pragma unroll
        for (int n = 0; n < 4; ++n)
#pragma unroll
            for (int q = 0; q < 4; ++q) acc[m][n][q] = 0.f;

    const float4* x4 = reinterpret_cast<const float4*>(x);
    const float4* B4 = reinterpret_cast<const float4*>(Bm);

    for (int kc = 0; kc < 2; ++kc) {
        if (kc) __syncthreads();
        // Stage x chunk: 128 t x 16 float4, tf32 hi/lo split
#pragma unroll
        for (int i = 0; i < 8; ++i) {
            int f  = tid + 256 * i;
            int t  = f >> 4;
            int jq = f & 15;
            float4 v = x4[(b * TT + t0 + t) * 32 + kc * 16 + jq];
            float4 hv, lv;
            hv.x = __uint_as_float(tf32bits(v.x)); lv.x = v.x - hv.x;
            hv.y = __uint_as_float(tf32bits(v.y)); lv.y = v.y - hv.y;
            hv.z = __uint_as_float(tf32bits(v.z)); lv.z = v.z - hv.z;
            hv.w = __uint_as_float(tf32bits(v.w)); lv.w = v.w - hv.w;
            *reinterpret_cast<float4*>(&xhi[t * KST + jq * 4]) = hv;
            *reinterpret_cast<float4*>(&xlo[t * KST + jq * 4]) = lv;
        }
        // Stage B chunk: 64 h x 16 float4
#pragma unroll
        for (int i = 0; i < 4; ++i) {
            int f  = tid + 256 * i;
            int h  = f >> 4;
            int jq = f & 15;
            float4 v = B4[h * 32 + kc * 16 + jq];
            float4 hv, lv;
            hv.x = __uint_as_float(tf32bits(v.x)); lv.x = v.x - hv.x;
            hv.y = __uint_as_float(tf32bits(v.y)); lv.y = v.y - hv.y;
            hv.z = __uint_as_float(tf32bits(v.z)); lv.z = v.z - hv.z;
            hv.w = __uint_as_float(tf32bits(v.w)); lv.w = v.w - hv.w;
            *reinterpret_cast<float4*>(&bhi[h * KST + jq * 4]) = hv;
            *reinterpret_cast<float4*>(&blo[h * KST + jq * 4]) = lv;
        }
        __syncthreads();

#pragma unroll
        for (int ks = 0; ks < 8; ++ks) {
            const int j0 = ks * 8;
            unsigned ah[2][4], al[2][4];
#pragma unroll
            for (int m = 0; m < 2; ++m) {
                int base = (wt * 32 + m * 16 + lr) * KST + j0 + lc;
                ah[m][0] = fbits(xhi[base]);
                ah[m][1] = fbits(xhi[base + 8 * KST]);
                ah[m][2] = fbits(xhi[base + 4]);
                ah[m][3] = fbits(xhi[base + 8 * KST + 4]);
                al[m][0] = fbits(xlo[base]);
                al[m][1] = fbits(xlo[base + 8 * KST]);
                al[m][2] = fbits(xlo[base + 4]);
                al[m][3] = fbits(xlo[base + 8 * KST + 4]);
            }
#pragma unroll
            for (int n = 0; n < 4; ++n) {
                int hb = (wh * 32 + n * 8 + lr) * KST + j0 + lc;
                unsigned bh0 = fbits(bhi[hb]);
                unsigned bh1 = fbits(bhi[hb + 4]);
                unsigned bl0 = fbits(blo[hb]);
                unsigned bl1 = fbits(blo[hb + 4]);
#pragma unroll
                for (int m = 0; m < 2; ++m) {
                    mma_tf32(acc[m][n][0], acc[m][n][1], acc[m][n][2], acc[m][n][3],
                             ah[m][0], ah[m][1], ah[m][2], ah[m][3], bh0, bh1);
                    mma_tf32(acc[m][n][0], acc[m][n][1], acc[m][n][2], acc[m][n][3],
                             ah[m][0], ah[m][1], ah[m][2], ah[m][3], bl0, bl1);
                    mma_tf32(acc[m][n][0], acc[m][n][1], acc[m][n][2], acc[m][n][3],
                             al[m][0], al[m][1], al[m][2], al[m][3], bh0, bh1);
                }
            }
        }
    }
    __syncthreads();

    // Stage D = Bx into smem as [t][h], stride 65 (aliases staging region).
    float* sD = sm;
#pragma unroll
    for (int m = 0; m < 2; ++m)
#pragma unroll
        for (int n = 0; n < 4; ++n) {
            int tr = wt * 32 + m * 16 + lr;
            int hc = wh * 32 + n * 8 + 2 * lc;
            sD[tr * 65 + hc]           = acc[m][n][0];
            sD[tr * 65 + hc + 1]       = acc[m][n][1];
            sD[(tr + 8) * 65 + hc]     = acc[m][n][2];
            sD[(tr + 8) * 65 + hc + 1] = acc[m][n][3];
        }
    __syncthreads();

    // ---- Segment-local scan (zero initial state) ----
    const int h = tid & 63;
    const int c = tid >> 6;             // 0..3: 32-step chunk

    const float mag = expf(-expf(nu[h]));
    float sn, cs;
    sincosf(theta[h], &sn, &cs);
    const float Lr = mag * cs;
    const float Li = mag * sn;

    float u[32];
#pragma unroll
    for (int k = 0; k < 32; ++k) u[k] = sD[(c * 32 + k) * 65 + h];

    // Phase A: local chunk scan from zero -> chunk value V
    float yr = 0.f, yi = 0.f;
#pragma unroll
    for (int k = 0; k < 32; ++k) {
        float nyr = fmaf(Lr, yr, fmaf(-Li, yi, u[k]));
        float nyi = fmaf(Lr, yi, Li * yr);
        yr = nyr; yi = nyi;
    }
    Vr_s[c * 64 + h] = yr;
    Vi_s[c * 64 + h] = yi;
    __syncthreads();

    // Combine (tid<64): P = lam^32; chunk prefixes + segment carry -> g_C.
    if (tid < 64) {
        float Pr = Lr, Pi = Li;
#pragma unroll
        for (int s = 0; s < 5; ++s) {
            float nr = Pr * Pr - Pi * Pi;
            float ni = 2.f * Pr * Pi;
            Pr = nr; Pi = ni;
        }
        float wr = 0.f, wi = 0.f;
        Wr_s[h] = 0.f; Wi_s[h] = 0.f;
#pragma unroll
        for (int cc = 1; cc < 4; ++cc) {
            float vr = Vr_s[(cc - 1) * 64 + h];
            float vi = Vi_s[(cc - 1) * 64 + h];
            float nwr = vr + (Pr * wr - Pi * wi);
            float nwi = vi + (Pr * wi + Pi * wr);
            wr = nwr; wi = nwi;
            Wr_s[cc * 64 + h] = wr;
            Wi_s[cc * 64 + h] = wi;
        }
        float vr = Vr_s[3 * 64 + h];
        float vi = Vi_s[3 * 64 + h];
        float Cr = vr + (Pr * wr - Pi * wi);
        float Ci = vi + (Pr * wi + Pi * wr);
        g_C[(b * 8 + ts) * 64 + h] = make_float2(Cr, Ci);
    }
    __syncthreads();

    // Phase C: zero-state outputs (fixup adds the cross-segment correction).
    yr = Wr_s[c * 64 + h];
    yi = Wi_s[c * 64 + h];
    float* op = out + (b * TT + t0 + c * 32) * (2 * HH) + h;
#pragma unroll
    for (int k = 0; k < 32; ++k) {
        float nyr = fmaf(Lr, yr, fmaf(-Li, yi, u[k]));
        float nyi = fmaf(Lr, yi, Li * yr);
        yr = nyr; yi = nyi;
        op[k * 128]      = yr;   // re at [b,t,h]
        op[k * 128 + 64] = yi;   // im at [b,t,H+h]
    }
}

// ---------------------------------------------------------------------------
// Prep: one thread per (k,h) table entry AND per (b,seg,h) state item.
// 64 blocks x 128 threads = 8192 threads.
//   Table:  g_L[(k-1)*64+h] = lam_h^k           (closed form)
//   State:  g_S[(b*8+seg)*64+h] = Horner(Q, C)  (<=7 complex FMAs, ONCE)
// ---------------------------------------------------------------------------
__global__ __launch_bounds__(128) void prep_kernel(const float* __restrict__ nu,
                                                   const float* __restrict__ theta) {
    const int gid = blockIdx.x * 128 + threadIdx.x;   // 0..8191
    const int h   = gid & 63;
    const int kk  = (gid >> 6) + 1;                   // 1..128

    const float enu = expf(nu[h]);
    const float th  = theta[h];

    // Table entry lam^kk
    {
        float m = expf(-(float)kk * enu);
        float s, c;
        sincosf((float)kk * th, &s, &c);
        g_L[(kk - 1) * 64 + h] = make_float2(m * c, m * s);
    }

    // State entry: b = gid>>9, seg = (gid>>6)&7
    const int b   = gid >> 9;
    const int seg = (gid >> 6) & 7;
    float mq = expf(-128.f * enu);
    float sq, cq;
    sincosf(128.f * th, &sq, &cq);
    const float Qr = mq * cq, Qi = mq * sq;
    float Sr = 1.f, Si = 0.f;
    for (int g = 0; g < seg; ++g) {
        float2 cg = g_C[(b * 8 + g) * 64 + h];
        float nr = Qr * Sr - Qi * Si + cg.x;
        float ni = Qr * Si + Qi * Sr + cg.y;
        Sr = nr; Si = ni;
    }
    g_S[(b * 8 + seg) * 64 + h] = make_float2(Sr, Si);
}

// ---------------------------------------------------------------------------
// Fixup: out[b,t,h] += lam_h^(tl+1) * S(b,seg,h).  Chain-free: S and lam^k
// are table loads (L2-hot); 4 independent t per thread for ILP.
// 256 blocks x 256 threads.
// ---------------------------------------------------------------------------
__global__ __launch_bounds__(256) void fixup_kernel(float* __restrict__ out) {
    const int tid = threadIdx.x;
    const int bx  = blockIdx.x;         // 0..255
    const int b   = bx >> 4;
    const int tb  = bx & 15;            // 64-t block
    const int tt  = tid >> 4;           // 0..15
    const int hq  = tid & 15;
    const int h0  = hq * 4;
    const int t0  = tb * 64 + tt * 4;   // 4 consecutive t, same segment
    const int seg = t0 >> 7;

    // S for 4 h (uniform per (block, h0): L2 broadcast)
    const float4* Sp = reinterpret_cast<const float4*>(&g_S[(b * 8 + seg) * 64 + h0]);
    float4 s01 = Sp[0], s23 = Sp[1];
    const float Sr[4] = {s01.x, s01.z, s23.x, s23.z};
    const float Si[4] = {s01.y, s01.w, s23.y, s23.w};

#pragma unroll
    for (int i = 0; i < 4; ++i) {
        const int t = t0 + i;
        const int k = (t & 127) + 1;
        const float4* Lp = reinterpret_cast<const float4*>(&g_L[(k - 1) * 64 + h0]);
        float4 l01 = Lp[0], l23 = Lp[1];
        float lkr[4] = {l01.x, l01.z, l23.x, l23.z};
        float lki[4] = {l01.y, l01.w, l23.y, l23.w};

        float* p = out + (b * TT + t) * (2 * HH) + h0;
        float4 re = *reinterpret_cast<float4*>(p);
        float4 im = *reinterpret_cast<float4*>(p + 64);
        re.x += lkr[0] * Sr[0] - lki[0] * Si[0];
        re.y += lkr[1] * Sr[1] - lki[1] * Si[1];
        re.z += lkr[2] * Sr[2] - lki[2] * Si[2];
        re.w += lkr[3] * Sr[3] - lki[3] * Si[3];
        im.x += lkr[0] * Si[0] + lki[0] * Sr[0];
        im.y += lkr[1] * Si[1] + lki[1] * Sr[1];
        im.z += lkr[2] * Si[2] + lki[2] * Sr[2];
        im.w += lkr[3] * Si[3] + lki[3] * Sr[3];
        *reinterpret_cast<float4*>(p)      = re;
        *reinterpret_cast<float4*>(p + 64) = im;
    }
}

// ---------------------------------------------------------------------------
extern "C" void kernel_launch(void* const* d_in, const int* in_sizes, int n_in,
                              void* d_out, int out_size) {
    const float* x     = (const float*)d_in[0];   // [16,1024,128]
    const float* Bm    = (const float*)d_in[1];   // [64,128]
    const float* nu    = (const float*)d_in[2];   // [64]
    const float* theta = (const float*)d_in[3];   // [64]
    float* out = (float*)d_out;                   // [16,1024,128]

    cudaFuncSetAttribute(fused_kernel,
                         cudaFuncAttributeMaxDynamicSharedMemorySize,
                         K1_SMEM_BYTES);
    fused_kernel<<<128, 256, K1_SMEM_BYTES>>>(x, Bm, nu, theta, out);
    prep_kernel<<<64, 128>>>(nu, theta);
    fixup_kernel<<<256, 256>>>(out);
}